// round 12
// baseline (speedup 1.0000x reference)
#include <cuda_runtime.h>
#include <cuda_bf16.h>
#include <math.h>

#define BB 16
#define NN 25200
#define KPRE 1024
#define MAXDET 300
#define OUTC 89
#define UTW 16896   // upper-triangle words per batch: 32 * (32+31+...+1) = 32*528
#define APB 24      // anchors per k_score block (NN % 24 == 0 -> 1050 blocks/batch)

// candidate key: [score_bits:32][(NN - anchor):15][class:7]
//   -> descending u64 order == (score desc, anchor asc); class never affects order.
// g_top entry:   [score_bits:32][class:7 @bit15][anchor:15 @bit0]

// ---------------- scratch (device globals; zero-initialized at load) ----------------
__device__ unsigned           g_cnt[BB];                 // zeroed at end of k_sortsel
__device__ unsigned long long g_cand[BB*NN];
__device__ unsigned long long g_top[BB*KPRE];
__device__ float4             g_boxes[BB*KPRE];
__device__ unsigned           g_validw[BB*32];
__device__ unsigned           g_maskut[BB*UTW];          // compacted upper-triangle mask
__device__ int                g_sel[BB*MAXDET];
__device__ int                g_nk[BB];

static __device__ __forceinline__ int score_bin(unsigned bits) {
    int bin = (int)(bits >> 16) - 0x3E00;
    return bin < 0 ? 0 : (bin > 511 ? 511 : bin);
}

// tile start (in words) of the compacted upper-triangle layout
static __device__ __forceinline__ int ut_tilestart(int t) {
    return 32 * (32*t - (t*(t-1))/2);
}

// ---------------- phase 1: dense uint4-streamed score/argmax ----------------
// block = 256 threads, owns APB=24 consecutive anchors of one batch.
__global__ void k_score(const float* __restrict__ pred) {
    __shared__ float srow[APB*85];               // 2040 floats = 8160 B
    __shared__ unsigned long long sbuf[APB];
    __shared__ unsigned scnt;
    __shared__ unsigned sbase;
    int tid = threadIdx.x;
    int b = blockIdx.y;
    int a0 = blockIdx.x * APB;
    if (tid == 0) scnt = 0;

    // dense 16B-aligned streaming load: 2040 floats = 510 uint4
    const uint4* gp = (const uint4*)(pred + ((size_t)b*NN + a0) * 85);
    uint4* sp = (uint4*)srow;
    #pragma unroll
    for (int i = tid; i < 510; i += 256) sp[i] = gp[i];
    __syncthreads();

    int wid = tid >> 5, lane = tid & 31;
    #pragma unroll
    for (int k = 0; k < 3; k++) {
        int row = wid*3 + k;                     // 8 warps * 3 rows = 24
        const float* rp = &srow[row*85];
        float obj = rp[4];
        if (obj > 0.4f) {                        // warp-uniform (same smem word)
            float l0 = rp[lane];
            float l1 = rp[32 + lane];
            float l2 = (lane < 21) ? rp[64 + lane] : 0.f;
            // per-lane best in ascending class order; strict > keeps smallest class on ties
            float bv; int bi;
            if (lane >= 5) { bv = l0 * obj; bi = lane - 5; }     // classes 0..26
            else           { bv = -1.f;     bi = 127; }
            { float p = l1 * obj; if (p > bv) { bv = p; bi = 27 + lane; } }   // 27..58
            if (lane < 21) { float p = l2 * obj; if (p > bv) { bv = p; bi = 59 + lane; } } // 59..79

            unsigned u = __float_as_uint(bv);    // bv >= 0 for all lanes after l1 step
            unsigned mmax = __reduce_max_sync(0xffffffffu, u);
            unsigned mcls = __reduce_min_sync(0xffffffffu, (u == mmax) ? (unsigned)bi : 0xFFu);

            if (lane == 0 && __uint_as_float(mmax) > 0.4f) {
                unsigned anchor = (unsigned)(a0 + row);
                unsigned long long key = ((unsigned long long)mmax << 32)
                                       | ((unsigned long long)((unsigned)NN - anchor) << 7)
                                       | (unsigned long long)mcls;
                unsigned p = atomicAdd(&scnt, 1u);
                sbuf[p] = key;
            }
        }
    }
    __syncthreads();
    if (tid == 0 && scnt) sbase = atomicAdd(&g_cnt[b], scnt);
    __syncthreads();
    if (tid < scnt)
        g_cand[(size_t)b*NN + sbase + tid] = sbuf[tid];
}

// ---------------- phase 2: per-batch hist + exact threshold + T-bin sort + 1024 sort ----------------
__global__ void k_sortsel(const float* __restrict__ pred) {
    __shared__ unsigned long long skA[1024];
    __shared__ unsigned long long tbuf[4096];
    __shared__ unsigned hist[512];
    __shared__ int sT;
    __shared__ unsigned nA, nB;
    int b = blockIdx.x, tid = threadIdx.x;   // 1024 threads

    skA[tid] = 0ull;
    for (int i = tid; i < 4096; i += 1024) tbuf[i] = 0ull;
    if (tid < 512) hist[tid] = 0u;
    if (tid == 0) { nA = 0; nB = 0; }
    __syncthreads();

    unsigned nc = min(g_cnt[b], (unsigned)NN);
    const unsigned long long* cand = &g_cand[(size_t)b*NN];
    for (unsigned i = tid; i < nc; i += 1024)
        atomicAdd(&hist[score_bin((unsigned)(cand[i] >> 32))], 1u);
    __syncthreads();
    for (int off = 1; off < 512; off <<= 1) {
        unsigned v = 0;
        if (tid < 512 && tid + off < 512) v = hist[tid + off];
        __syncthreads();
        if (tid < 512) hist[tid] += v;
        __syncthreads();
    }
    if (tid < 512) {
        unsigned suf  = hist[tid];
        unsigned sufn = (tid < 511) ? hist[tid + 1] : 0u;
        if (tid == 0 && suf < (unsigned)KPRE) sT = -1;
        if (suf >= (unsigned)KPRE && sufn < (unsigned)KPRE) sT = tid;
    }
    __syncthreads();
    int T = sT;
    for (unsigned i = tid; i < nc; i += 1024) {
        unsigned long long key = cand[i];
        int bin = score_bin((unsigned)(key >> 32));
        if (bin > T) {
            unsigned p = atomicAdd(&nA, 1u);
            if (p < 1024u) skA[p] = key;
        } else if (bin == T) {
            unsigned p = atomicAdd(&nB, 1u);
            if (p < 4096u) tbuf[p] = key;
        }
    }
    __syncthreads();
    unsigned m = min(nB, 4096u);
    if (m > 0u) {
        unsigned St = 32; while (St < m) St <<= 1;
        for (unsigned k2 = 2; k2 <= St; k2 <<= 1) {
            for (unsigned j = k2 >> 1; j > 0; j >>= 1) {
                for (unsigned i = tid; i < St; i += 1024) {
                    unsigned ixj = i ^ j;
                    if (ixj > i) {
                        bool up = ((i & k2) == 0);
                        unsigned long long x = tbuf[i], y = tbuf[ixj];
                        bool sw = up ? (x < y) : (x > y);
                        if (sw) { tbuf[i] = y; tbuf[ixj] = x; }
                    }
                }
                __syncthreads();
            }
        }
        unsigned a = nA;                 // < 1024 guaranteed by threshold choice
        unsigned needK = 1024u - a;
        if (tid < needK) skA[a + tid] = tbuf[tid];
        __syncthreads();
    }
    for (unsigned k2 = 2; k2 <= 1024; k2 <<= 1) {
        for (unsigned j = k2 >> 1; j > 0; j >>= 1) {
            unsigned i = tid, ixj = i ^ j;
            if (ixj > i) {
                bool up = ((i & k2) == 0);
                unsigned long long x = skA[i], y = skA[ixj];
                bool sw = up ? (x < y) : (x > y);
                if (sw) { skA[i] = y; skA[ixj] = x; }
            }
            __syncthreads();
        }
    }
    // emit top-1024: repacked key, boxes, valid bits
    {
        unsigned long long key = skA[tid];
        unsigned bits = (unsigned)(key >> 32);
        unsigned anchor = 0, cls = 0;
        if (bits) {
            anchor = (unsigned)NN - ((unsigned)(key >> 7) & 0x7FFFu);
            cls = (unsigned)key & 0x7Fu;
        }
        g_top[b*KPRE + tid] = ((unsigned long long)bits << 32) | (cls << 15) | anchor;
        float4 bx = make_float4(0.f, 0.f, 0.f, 0.f);
        if (bits) {
            size_t pb = ((size_t)b*NN + anchor) * 85;
            float x = pred[pb], y = pred[pb+1], w = pred[pb+2], h = pred[pb+3];
            float off = (float)cls * 4096.0f;
            bx.x = (x - w*0.5f) + off;
            bx.y = (y - h*0.5f) + off;
            bx.z = (x + w*0.5f) + off;
            bx.w = (y + h*0.5f) + off;
        }
        g_boxes[b*KPRE + tid] = bx;
        unsigned bal = __ballot_sync(0xffffffffu, bits != 0u);
        if ((tid & 31) == 0) g_validw[b*32 + (tid >> 5)] = bal;
    }
    __syncthreads();
    if (tid == 0) g_cnt[b] = 0;   // reset for next replay
}

// ---------------- phase 3: IoU bit-mask -> compacted upper-triangle layout ----------------
__global__ void k_iou() {
    __shared__ float4 sb[1024];
    __shared__ float  sa[1024];
    __shared__ unsigned tileS[32][33];
    int b = blockIdx.y, tile = blockIdx.x;
    int tid = threadIdx.x;
    float4 v = g_boxes[b*KPRE + tid];
    sb[tid] = v;
    sa[tid] = (v.z - v.x) * (v.w - v.y);
    __syncthreads();

    int w = tid >> 5, rl = tid & 31;
    int r = tile*32 + rl;
    unsigned bits = 0u;
    if (w >= tile) {   // lower-triangle words are identically zero (j>i only)
        float4 rb_ = sb[r];
        float  ra  = sa[r];
        int j0 = w * 32;
        #pragma unroll 4
        for (int t = 0; t < 32; t++) {
            int j = j0 + t;
            float4 cb = sb[j];
            float ltx = fmaxf(rb_.x, cb.x), lty = fmaxf(rb_.y, cb.y);
            float rbx = fminf(rb_.z, cb.z), rby = fminf(rb_.w, cb.w);
            float iw = fmaxf(rbx - ltx, 0.f), ih = fmaxf(rby - lty, 0.f);
            float inter = iw * ih;
            float den = ((ra + sa[j]) - inter) + 1e-7f;
            float thr = 0.45f * den;
            bool sup;
            if (inter > thr * (1.0f + 1e-5f))       sup = true;
            else if (inter < thr * (1.0f - 1e-5f))  sup = false;
            else                                    sup = (__fdiv_rn(inter, den) > 0.45f);
            sup = sup && (j > r);
            bits |= sup ? (1u << t) : 0u;
        }
        tileS[rl][w] = bits;
    }
    __syncthreads();
    // compacted store: row rl2 of this tile keeps words [tile, 32) only
    int nw = 32 - tile;
    int total = 32 * nw;
    int ts = ut_tilestart(tile);
    if (tid < total) {
        int rl2 = tid / nw, w2o = tid - rl2*nw;
        g_maskut[(size_t)b*UTW + ts + rl2*nw + w2o] = tileS[rl2][tile + w2o];
    }
}

// ---------------- phase 4: overlapped staging + speculative greedy scan ----------------
__global__ void k_nms() {
    extern __shared__ unsigned smu[];           // UTW words = 66 KB
    __shared__ volatile unsigned tflag[32];
    int b = blockIdx.x, tid = threadIdx.x;      // 1024 threads = 32 warps
    int wid = tid >> 5, lane = tid & 31;

    if (tid < 32) tflag[tid] = 0;
    __syncthreads();

    const uint4* mp4 = (const uint4*)&g_maskut[(size_t)b*UTW];
    uint4* sm4 = (uint4*)smu;

    if (wid > 0) {
        // warp w copies tile w-1; warp 1 additionally copies tiny tile 31
        for (int t = wid - 1; t < 32; t += 31) {
            int ts4 = ut_tilestart(t) >> 2;     // uint4 index (tilestart % 4 == 0)
            int n4  = 8 * (32 - t);             // uint4 count of tile t
            for (int i = lane; i < n4; i += 32)
                sm4[ts4 + i] = mp4[ts4 + i];
            __threadfence_block();
            if (lane == 0) tflag[t] = 1;
        }
        return;
    }

    // warp 0: greedy scan, consuming tiles in increasing wp order
    unsigned alive = g_validw[b*32 + lane];     // lane holds indices [lane*32, lane*32+32)
    int cnt = 0;
    unsigned bal = __ballot_sync(0xffffffffu, alive != 0u);
    while (cnt < MAXDET && bal) {
        int wp = __ffs(bal) - 1;
        while (tflag[wp] == 0) { }              // tile wp ready?
        __threadfence_block();
        int ts = ut_tilestart(wp);
        int nw = 32 - wp;
        unsigned curw = __shfl_sync(0xffffffffu, alive, wp);
        while (curw && cnt < MAXDET) {
            int bit = __ffs(curw) - 1;
            unsigned rest = curw & (curw - 1u);
            int ro1 = ts + bit * nw;            // row wp*32+bit, words [wp,32)
            unsigned rw1 = smu[ro1];            // broadcast: word wp of kept row
            // speculative prefetch of the next candidate's row (off critical path)
            int bit2 = 0; unsigned rw2 = 0u, rl2 = 0u; int ro2 = 0;
            if (rest) {
                bit2 = __ffs(rest) - 1;
                ro2 = ts + bit2 * nw;
                rw2 = smu[ro2];
                rl2 = (lane >= wp) ? smu[ro2 + lane - wp] : 0u;
            }
            unsigned rl1 = (lane >= wp) ? smu[ro1 + lane - wp] : 0u;
            alive &= ~rl1;
            if (lane == wp) alive &= ~(1u << bit);
            if (lane == 0) g_sel[b*MAXDET + cnt] = wp*32 + bit;
            cnt++;
            curw = rest & ~rw1;
            // speculation hit: bit2 not suppressed by bit -> consume with preloaded data
            if (rest && cnt < MAXDET && !(rw1 & (1u << bit2))) {
                alive &= ~rl2;
                if (lane == wp) alive &= ~(1u << bit2);
                if (lane == 0) g_sel[b*MAXDET + cnt] = wp*32 + bit2;
                cnt++;
                curw &= ~rw2;
                curw &= ~(1u << bit2);
            }
        }
        // words <= wp fully consumed; find next word with survivors
        bal = __ballot_sync(0xffffffffu, (lane > wp) && (alive != 0u));
    }
    if (lane == 0) g_nk[b] = cnt;
}

// ---------------- phase 5: gather + emit output rows (wide) ----------------
__global__ void k_out(const float* __restrict__ pred,
                      const float* __restrict__ conf_logits,
                      const float* __restrict__ logits,
                      const float* __restrict__ head,
                      float* __restrict__ out) {
    int gw = (blockIdx.x * blockDim.x + threadIdx.x) >> 5;
    int lane = threadIdx.x & 31;
    if (gw >= BB*MAXDET) return;
    int b = gw / MAXDET, r = gw - b*MAXDET;
    size_t obase = (size_t)gw * OUTC;
    int nk = g_nk[b];
    if (r < nk) {
        int slot = g_sel[b*MAXDET + r];
        unsigned long long key = g_top[b*KPRE + slot];
        float score = __uint_as_float((unsigned)(key >> 32));
        unsigned anchor = (unsigned)key & 0x7FFFu;
        unsigned cls = ((unsigned)key >> 15) & 0x7Fu;
        size_t a = (size_t)b*NN + anchor;
        float objsig = 1.f / (1.f + expf(-conf_logits[a*5 + 4]));
        for (int c = lane; c < OUTC; c += 32) {
            float val;
            if (c < 4) {
                float x = pred[a*85], y = pred[a*85+1], w = pred[a*85+2], h = pred[a*85+3];
                val = (c == 0) ? x - w*0.5f : (c == 1) ? y - h*0.5f
                    : (c == 2) ? x + w*0.5f : y + h*0.5f;
            } else if (c == 4)  val = score;
            else if (c == 5)    val = (float)cls;
            else if (c < 86)    val = (1.f / (1.f + expf(-logits[a*80 + (c - 6)]))) * objsig;
            else if (c == 86)   val = objsig;
            else if (c == 87)   val = head[a];
            else                val = 1.f;
            out[obase + c] = val;
        }
    } else {
        for (int c = lane; c < OUTC; c += 32) out[obase + c] = 0.f;
    }
}

extern "C" void kernel_launch(void* const* d_in, const int* in_sizes, int n_in,
                              void* d_out, int out_size) {
    const float* pred = (const float*)d_in[0];
    const float* cl   = (const float*)d_in[1];
    const float* lg   = (const float*)d_in[2];
    const float* hd   = (const float*)d_in[3];
    float* out = (float*)d_out;

    cudaFuncSetAttribute(k_nms, cudaFuncAttributeMaxDynamicSharedMemorySize,
                         UTW * (int)sizeof(unsigned));

    k_score<<<dim3(NN/APB, BB), 256>>>(pred);   // 1050 x 16 blocks
    k_sortsel<<<BB, 1024>>>(pred);
    k_iou<<<dim3(32, BB), 1024>>>();
    k_nms<<<BB, 1024, UTW * sizeof(unsigned)>>>();
    k_out<<<(BB*MAXDET*32 + 255) / 256, 256>>>(pred, cl, lg, hd, out);
}

// round 13
// speedup vs baseline: 1.0578x; 1.0578x over previous
#include <cuda_runtime.h>
#include <cuda_bf16.h>
#include <math.h>

#define BB 16
#define NN 25200
#define KPRE 1024
#define MAXDET 300
#define OUTC 89
#define UTW 16896   // upper-triangle words per batch: 32 * (32+31+...+1) = 32*528
#define APB 24      // anchors per k_score block (NN % 24 == 0 -> 1050 blocks/batch)

// candidate key: [score_bits:32][(NN - anchor):15][class:7]
//   -> descending u64 order == (score desc, anchor asc); class never affects order.
// g_top entry:   [score_bits:32][class:7 @bit15][anchor:15 @bit0]

// ---------------- scratch (device globals; zero-initialized at load) ----------------
__device__ unsigned           g_cnt[BB];                 // zeroed at end of k_sortsel
__device__ unsigned long long g_cand[BB*NN];
__device__ unsigned long long g_top[BB*KPRE];
__device__ float4             g_boxes[BB*KPRE];
__device__ unsigned           g_validw[BB*32];
__device__ unsigned           g_maskut[BB*UTW];          // compacted upper-triangle mask
__device__ int                g_sel[BB*MAXDET];
__device__ int                g_nk[BB];

static __device__ __forceinline__ int score_bin(unsigned bits) {
    int bin = (int)(bits >> 16) - 0x3E00;
    return bin < 0 ? 0 : (bin > 511 ? 511 : bin);
}

// tile start (in words) of the compacted upper-triangle layout
static __device__ __forceinline__ int ut_tilestart(int t) {
    return 32 * (32*t - (t*(t-1))/2);
}

// ---------------- phase 1: dense uint4-streamed score/argmax ----------------
// block = 256 threads, owns APB=24 consecutive anchors of one batch.
__global__ void k_score(const float* __restrict__ pred) {
    __shared__ float srow[APB*85];               // 2040 floats = 8160 B
    __shared__ unsigned long long sbuf[APB];
    __shared__ unsigned scnt;
    __shared__ unsigned sbase;
    int tid = threadIdx.x;
    int b = blockIdx.y;
    int a0 = blockIdx.x * APB;
    if (tid == 0) scnt = 0;

    // dense 16B-aligned streaming load: 2040 floats = 510 uint4
    const uint4* gp = (const uint4*)(pred + ((size_t)b*NN + a0) * 85);
    uint4* sp = (uint4*)srow;
    #pragma unroll
    for (int i = tid; i < 510; i += 256) sp[i] = gp[i];
    __syncthreads();

    int wid = tid >> 5, lane = tid & 31;
    #pragma unroll
    for (int k = 0; k < 3; k++) {
        int row = wid*3 + k;                     // 8 warps * 3 rows = 24
        const float* rp = &srow[row*85];
        float obj = rp[4];
        if (obj > 0.4f) {                        // warp-uniform (same smem word)
            float l0 = rp[lane];
            float l1 = rp[32 + lane];
            float l2 = (lane < 21) ? rp[64 + lane] : 0.f;
            // per-lane best in ascending class order; strict > keeps smallest class on ties
            float bv; int bi;
            if (lane >= 5) { bv = l0 * obj; bi = lane - 5; }     // classes 0..26
            else           { bv = -1.f;     bi = 127; }
            { float p = l1 * obj; if (p > bv) { bv = p; bi = 27 + lane; } }   // 27..58
            if (lane < 21) { float p = l2 * obj; if (p > bv) { bv = p; bi = 59 + lane; } } // 59..79

            unsigned u = __float_as_uint(bv);    // bv >= 0 for all lanes after l1 step
            unsigned mmax = __reduce_max_sync(0xffffffffu, u);
            unsigned mcls = __reduce_min_sync(0xffffffffu, (u == mmax) ? (unsigned)bi : 0xFFu);

            if (lane == 0 && __uint_as_float(mmax) > 0.4f) {
                unsigned anchor = (unsigned)(a0 + row);
                unsigned long long key = ((unsigned long long)mmax << 32)
                                       | ((unsigned long long)((unsigned)NN - anchor) << 7)
                                       | (unsigned long long)mcls;
                unsigned p = atomicAdd(&scnt, 1u);
                sbuf[p] = key;
            }
        }
    }
    __syncthreads();
    if (tid == 0 && scnt) sbase = atomicAdd(&g_cnt[b], scnt);
    __syncthreads();
    if (tid < scnt)
        g_cand[(size_t)b*NN + sbase + tid] = sbuf[tid];
}

// ---------------- phase 2: per-batch hist + exact threshold + T-bin sort + 1024 sort ----------------
__global__ void k_sortsel(const float* __restrict__ pred) {
    __shared__ unsigned long long skA[1024];
    __shared__ unsigned long long tbuf[4096];
    __shared__ unsigned hist[512];
    __shared__ int sT;
    __shared__ unsigned sM;
    __shared__ unsigned nA, nB;
    int b = blockIdx.x, tid = threadIdx.x;   // 1024 threads

    skA[tid] = 0ull;
    if (tid < 512) hist[tid] = 0u;
    if (tid == 0) { nA = 0; nB = 0; }
    __syncthreads();

    unsigned nc = min(g_cnt[b], (unsigned)NN);
    const unsigned long long* cand = &g_cand[(size_t)b*NN];
    for (unsigned i = tid; i < nc; i += 1024)
        atomicAdd(&hist[score_bin((unsigned)(cand[i] >> 32))], 1u);
    __syncthreads();
    for (int off = 1; off < 512; off <<= 1) {
        unsigned v = 0;
        if (tid < 512 && tid + off < 512) v = hist[tid + off];
        __syncthreads();
        if (tid < 512) hist[tid] += v;
        __syncthreads();
    }
    if (tid < 512) {
        unsigned suf  = hist[tid];
        unsigned sufn = (tid < 511) ? hist[tid + 1] : 0u;
        if (tid == 0 && suf < (unsigned)KPRE) { sT = -1; sM = 0; }
        if (suf >= (unsigned)KPRE && sufn < (unsigned)KPRE) { sT = tid; sM = suf - sufn; }
    }
    __syncthreads();
    int T = sT;
    unsigned m = min(sM, 4096u);                 // exact T-bin count (capped)
    unsigned St = 32; while (St < m) St <<= 1;   // sort width, known pre-scatter
    for (unsigned i = tid; i < St; i += 1024) tbuf[i] = 0ull;
    __syncthreads();
    for (unsigned i = tid; i < nc; i += 1024) {
        unsigned long long key = cand[i];
        int bin = score_bin((unsigned)(key >> 32));
        if (bin > T) {
            unsigned p = atomicAdd(&nA, 1u);
            if (p < 1024u) skA[p] = key;
        } else if (bin == T) {
            unsigned p = atomicAdd(&nB, 1u);
            if (p < 4096u) tbuf[p] = key;
        }
    }
    __syncthreads();
    if (m > 0u) {
        for (unsigned k2 = 2; k2 <= St; k2 <<= 1) {
            for (unsigned j = k2 >> 1; j > 0; j >>= 1) {
                for (unsigned i = tid; i < St; i += 1024) {
                    unsigned ixj = i ^ j;
                    if (ixj > i) {
                        bool up = ((i & k2) == 0);
                        unsigned long long x = tbuf[i], y = tbuf[ixj];
                        bool sw = up ? (x < y) : (x > y);
                        if (sw) { tbuf[i] = y; tbuf[ixj] = x; }
                    }
                }
                __syncthreads();
            }
        }
        unsigned a = nA;                 // < 1024 guaranteed by threshold choice
        unsigned needK = 1024u - a;
        if (tid < needK && tid < St) skA[a + tid] = tbuf[tid];
        __syncthreads();
    }
    for (unsigned k2 = 2; k2 <= 1024; k2 <<= 1) {
        for (unsigned j = k2 >> 1; j > 0; j >>= 1) {
            unsigned i = tid, ixj = i ^ j;
            if (ixj > i) {
                bool up = ((i & k2) == 0);
                unsigned long long x = skA[i], y = skA[ixj];
                bool sw = up ? (x < y) : (x > y);
                if (sw) { skA[i] = y; skA[ixj] = x; }
            }
            __syncthreads();
        }
    }
    // emit top-1024: repacked key, boxes, valid bits
    {
        unsigned long long key = skA[tid];
        unsigned bits = (unsigned)(key >> 32);
        unsigned anchor = 0, cls = 0;
        if (bits) {
            anchor = (unsigned)NN - ((unsigned)(key >> 7) & 0x7FFFu);
            cls = (unsigned)key & 0x7Fu;
        }
        g_top[b*KPRE + tid] = ((unsigned long long)bits << 32) | (cls << 15) | anchor;
        float4 bx = make_float4(0.f, 0.f, 0.f, 0.f);
        if (bits) {
            size_t pb = ((size_t)b*NN + anchor) * 85;
            float x = pred[pb], y = pred[pb+1], w = pred[pb+2], h = pred[pb+3];
            float off = (float)cls * 4096.0f;
            bx.x = (x - w*0.5f) + off;
            bx.y = (y - h*0.5f) + off;
            bx.z = (x + w*0.5f) + off;
            bx.w = (y + h*0.5f) + off;
        }
        g_boxes[b*KPRE + tid] = bx;
        unsigned bal = __ballot_sync(0xffffffffu, bits != 0u);
        if ((tid & 31) == 0) g_validw[b*32 + (tid >> 5)] = bal;
    }
    __syncthreads();
    if (tid == 0) g_cnt[b] = 0;   // reset for next replay
}

// ---------------- phase 3: IoU bit-mask, tile-pair packed blocks ----------------
// block bx=0: tile 0 (32 warps); bx=1..15: tiles (bx, 32-bx) (31..17 + 1..15 warps);
// bx=16: tile 16 (16 warps). 17 blocks/batch, ~97% warp utilization.
__global__ void k_iou() {
    __shared__ float4 sb[1024];
    __shared__ float  sa[1024];
    __shared__ unsigned tS0[32][33];
    __shared__ unsigned tS1[32][33];
    int b = blockIdx.y, bx = blockIdx.x;
    int tid = threadIdx.x;
    float4 v = g_boxes[b*KPRE + tid];
    sb[tid] = v;
    sa[tid] = (v.z - v.x) * (v.w - v.y);
    __syncthreads();

    int t0 = bx;                         // bx=0..16
    int nw0 = 32 - t0;
    int t1 = (bx >= 1 && bx <= 15) ? 32 - bx : -1;
    int nw1 = (t1 >= 0) ? 32 - t1 : 0;

    int w = tid >> 5, lane = tid & 31;
    int tile = -1, wcol = 0;
    if (w < nw0)              { tile = t0; wcol = t0 + w; }
    else if (w < nw0 + nw1)   { tile = t1; wcol = t1 + (w - nw0); }

    if (tile >= 0) {
        int r = tile*32 + lane;
        float4 rb_ = sb[r];
        float  ra  = sa[r];
        unsigned bits = 0u;
        int j0 = wcol * 32;
        #pragma unroll 4
        for (int t = 0; t < 32; t++) {
            int j = j0 + t;
            float4 cb = sb[j];
            float ltx = fmaxf(rb_.x, cb.x), lty = fmaxf(rb_.y, cb.y);
            float rbx = fminf(rb_.z, cb.z), rby = fminf(rb_.w, cb.w);
            float iw = fmaxf(rbx - ltx, 0.f), ih = fmaxf(rby - lty, 0.f);
            float inter = iw * ih;
            float den = ((ra + sa[j]) - inter) + 1e-7f;
            float thr = 0.45f * den;
            bool sup;
            if (inter > thr * (1.0f + 1e-5f))       sup = true;
            else if (inter < thr * (1.0f - 1e-5f))  sup = false;
            else                                    sup = (__fdiv_rn(inter, den) > 0.45f);
            sup = sup && (j > r);
            bits |= sup ? (1u << t) : 0u;
        }
        if (tile == t0) tS0[lane][wcol - t0] = bits;
        else            tS1[lane][wcol - t1] = bits;
    }
    __syncthreads();
    // coalesced compacted stores: tile t rows are [ts + rl*nw, +nw)
    {
        int ts0 = ut_tilestart(t0);
        int tot0 = 32 * nw0;
        for (int i = tid; i < tot0; i += 1024) {
            int rl = i / nw0, off = i - rl*nw0;
            g_maskut[(size_t)b*UTW + ts0 + i] = tS0[rl][off];
        }
        if (t1 >= 0) {
            int ts1 = ut_tilestart(t1);
            int tot1 = 32 * nw1;
            for (int i = tid; i < tot1; i += 1024) {
                int rl = i / nw1, off = i - rl*nw1;
                g_maskut[(size_t)b*UTW + ts1 + i] = tS1[rl][off];
            }
        }
    }
}

// ---------------- phase 4: greedy scan over compacted smem mask ----------------
__global__ void k_nms() {
    extern __shared__ unsigned smu[];           // UTW words = 66 KB
    int b = blockIdx.x, tid = threadIdx.x;      // 1024 threads
    const uint4* mp4 = (const uint4*)&g_maskut[(size_t)b*UTW];
    uint4* sm4 = (uint4*)smu;
    for (int i = tid; i < UTW/4; i += 1024)     // 4224 uint4
        sm4[i] = mp4[i];
    __syncthreads();

    if (tid < 32) {
        int lane = tid;
        unsigned alive = g_validw[b*32 + lane];   // lane holds indices [lane*32, lane*32+32)
        int cnt = 0;
        unsigned bal = __ballot_sync(0xffffffffu, alive != 0u);
        while (cnt < MAXDET && bal) {
            int wp = __ffs(bal) - 1;
            int ts = ut_tilestart(wp);
            int nw = 32 - wp;
            unsigned curw = __shfl_sync(0xffffffffu, alive, wp);
            while (curw && cnt < MAXDET) {
                int bit = __ffs(curw) - 1;
                int rowoff = ts + bit * nw;            // row i = wp*32+bit, words [wp,32)
                unsigned rw = smu[rowoff];             // broadcast: word wp of row i
                unsigned rl_w = (lane >= wp) ? smu[rowoff + lane - wp] : 0u;
                curw &= ~rw;
                curw &= ~(1u << bit);
                alive &= ~rl_w;
                if (lane == wp) alive &= ~(1u << bit);
                if (lane == 0) g_sel[b*MAXDET + cnt] = wp*32 + bit;
                cnt++;
            }
            // words <= wp fully consumed; find next word with survivors
            bal = __ballot_sync(0xffffffffu, (lane > wp) && (alive != 0u));
        }
        if (lane == 0) g_nk[b] = cnt;
    }
}

// ---------------- phase 5: gather + emit output rows (wide) ----------------
__global__ void k_out(const float* __restrict__ pred,
                      const float* __restrict__ conf_logits,
                      const float* __restrict__ logits,
                      const float* __restrict__ head,
                      float* __restrict__ out) {
    int gw = (blockIdx.x * blockDim.x + threadIdx.x) >> 5;
    int lane = threadIdx.x & 31;
    if (gw >= BB*MAXDET) return;
    int b = gw / MAXDET, r = gw - b*MAXDET;
    size_t obase = (size_t)gw * OUTC;
    int nk = g_nk[b];
    if (r < nk) {
        int slot = g_sel[b*MAXDET + r];
        unsigned long long key = g_top[b*KPRE + slot];
        float score = __uint_as_float((unsigned)(key >> 32));
        unsigned anchor = (unsigned)key & 0x7FFFu;
        unsigned cls = ((unsigned)key >> 15) & 0x7Fu;
        size_t a = (size_t)b*NN + anchor;
        float objsig = 1.f / (1.f + expf(-conf_logits[a*5 + 4]));
        for (int c = lane; c < OUTC; c += 32) {
            float val;
            if (c < 4) {
                float x = pred[a*85], y = pred[a*85+1], w = pred[a*85+2], h = pred[a*85+3];
                val = (c == 0) ? x - w*0.5f : (c == 1) ? y - h*0.5f
                    : (c == 2) ? x + w*0.5f : y + h*0.5f;
            } else if (c == 4)  val = score;
            else if (c == 5)    val = (float)cls;
            else if (c < 86)    val = (1.f / (1.f + expf(-logits[a*80 + (c - 6)]))) * objsig;
            else if (c == 86)   val = objsig;
            else if (c == 87)   val = head[a];
            else                val = 1.f;
            out[obase + c] = val;
        }
    } else {
        for (int c = lane; c < OUTC; c += 32) out[obase + c] = 0.f;
    }
}

extern "C" void kernel_launch(void* const* d_in, const int* in_sizes, int n_in,
                              void* d_out, int out_size) {
    const float* pred = (const float*)d_in[0];
    const float* cl   = (const float*)d_in[1];
    const float* lg   = (const float*)d_in[2];
    const float* hd   = (const float*)d_in[3];
    float* out = (float*)d_out;

    cudaFuncSetAttribute(k_nms, cudaFuncAttributeMaxDynamicSharedMemorySize,
                         UTW * (int)sizeof(unsigned));

    k_score<<<dim3(NN/APB, BB), 256>>>(pred);   // 1050 x 16 blocks
    k_sortsel<<<BB, 1024>>>(pred);
    k_iou<<<dim3(17, BB), 1024>>>();            // tile-pair packed
    k_nms<<<BB, 1024, UTW * sizeof(unsigned)>>>();
    k_out<<<(BB*MAXDET*32 + 255) / 256, 256>>>(pred, cl, lg, hd, out);
}